// round 8
// baseline (speedup 1.0000x reference)
#include <cuda_runtime.h>
#include <cstdint>

typedef unsigned int u32;

// LSTM B=65536, T=20, I=36, H=30. Gate order i,f,g,o.
// Output: out[B,T,H] ++ h_n[1,B,H] ++ c_n[1,B,H], fp32.
//
// mma.sync m16n8k16 bf16, 3-pass hi/lo compensation, M=32 per warp.
// j-outer restructure: A-frags (80 regs) built once per t, D[8] transient,
// per-tile epilogue overlaps MUFU with next tile's MMAs. PITCH=68 slab
// -> 73.3KB smem -> 3 CTAs/SM (12 warps).

#define NB   65536
#define NT   20
#define NIn  36
#define NH   30

#define BLOCK 128                 // 4 warps, 128 batches per CTA
#define GRID  (NB / 128)          // 512

#define PITCH 68                  // x 0..35 | h 36..65 | bias 66 | zero 67
#define SLAB_FLOATS (32 * PITCH)  // 2176
#define SLAB_BYTES  (SLAB_FLOATS * 4)   // 8704
#define NCHUNK 5                  // K = 80 (cols >= 67 have B = 0)
#define NTILE  15                 // N = 120 = 15 x 8, n = hh*4 + gate

#define B_ENTRIES (NCHUNK * NTILE * 32)       // 2400 uint4
#define OFF_SLAB  (B_ENTRIES * 16)            // 38400 bytes
#define SMEM_BYTES (OFF_SLAB + 4 * SLAB_BYTES + 64)   // 73280 (tail pad)

__device__ __forceinline__ u32 bf16hi_u(float v) {
    return (__float_as_uint(v) + 0x8000u) & 0xFFFF0000u;
}
__device__ __forceinline__ u32 prmt_pack(u32 even_hi, u32 odd_hi) {
    u32 d;
    asm("prmt.b32 %0, %1, %2, 0x7632;" : "=r"(d) : "r"(even_hi), "r"(odd_hi));
    return d;
}
__device__ __forceinline__ u32 bf16x2_rn(float even, float odd) {
    u32 d;
    asm("cvt.rn.bf16x2.f32 %0, %1, %2;" : "=r"(d) : "f"(odd), "f"(even));
    return d;
}
__device__ __forceinline__ void mma_bf16(float* d, u32 a0, u32 a1, u32 a2, u32 a3,
                                         u32 b0, u32 b1) {
    asm volatile(
        "mma.sync.aligned.m16n8k16.row.col.f32.bf16.bf16.f32 "
        "{%0,%1,%2,%3}, {%4,%5,%6,%7}, {%8,%9}, {%0,%1,%2,%3};"
        : "+f"(d[0]), "+f"(d[1]), "+f"(d[2]), "+f"(d[3])
        : "r"(a0), "r"(a1), "r"(a2), "r"(a3), "r"(b0), "r"(b1));
}
__device__ __forceinline__ void mk_ahl(float2 f, u32& hi, u32& lo) {
    u32 he = bf16hi_u(f.x), ho = bf16hi_u(f.y);
    hi = prmt_pack(he, ho);
    lo = bf16x2_rn(f.x - __uint_as_float(he), f.y - __uint_as_float(ho));
}

__device__ __forceinline__ float sigmoid_f(float v) {
    return __fdividef(1.0f, 1.0f + __expf(-v));
}
__device__ __forceinline__ float tanh_f(float v) {
    return __fdividef(2.0f, 1.0f + __expf(-2.0f * v)) - 1.0f;
}

__device__ __forceinline__ u32 s2u(const void* p) {
    u32 a;
    asm("{ .reg .u64 t; cvta.to.shared.u64 t, %1; cvt.u32.u64 %0, t; }"
        : "=r"(a) : "l"(p));
    return a;
}
#define CP16(dst, src) \
    asm volatile("cp.async.ca.shared.global [%0], [%1], 16;" :: "r"(dst), "l"(src))
#define CP_COMMIT() asm volatile("cp.async.commit_group;" ::: "memory")
#define CP_WAIT0()  asm volatile("cp.async.wait_group 0;" ::: "memory")

// concatenated weight matrix: row n (gate-interleaved), col k in [0,80)
__device__ __forceinline__ float wcat(int n, int k,
                                      const float* W_ih, const float* W_hh,
                                      const float* b_ih, const float* b_hh) {
    int g = n & 3, hh = n >> 2;
    int row = g * NH + hh;
    if (k < 36) return W_ih[row * NIn + k];
    if (k < 66) return W_hh[row * NH + (k - 36)];
    if (k == 66) return b_ih[row] + b_hh[row];
    return 0.0f;
}

__global__ void __launch_bounds__(BLOCK, 3)
lstm_hmma_jo(const float* __restrict__ x,
             const float* __restrict__ W_ih,
             const float* __restrict__ W_hh,
             const float* __restrict__ b_ih,
             const float* __restrict__ b_hh,
             float* __restrict__ out) {
    extern __shared__ __align__(16) char smraw[];
    uint4* Bs   = reinterpret_cast<uint4*>(smraw);
    float* slab = reinterpret_cast<float*>(smraw + OFF_SLAB) + (threadIdx.x >> 5) * SLAB_FLOATS;

    const int tid  = threadIdx.x;
    const int lane = tid & 31;
    const int wB   = blockIdx.x * 128 + (tid >> 5) * 32;   // warp's first batch
    const u32 slab_u = s2u(slab);

    // ---- one-time B fragment prep (hi/lo bf16x2, per-lane layout) ----
    for (int idx = tid; idx < B_ENTRIES; idx += BLOCK) {
        int ch  = idx / (NTILE * 32);
        int rem = idx - ch * NTILE * 32;
        int j   = rem >> 5, ln = rem & 31;
        int n   = j * 8 + (ln >> 2);
        int kb  = 16 * ch + 2 * (ln & 3);
        float w00 = wcat(n, kb,     W_ih, W_hh, b_ih, b_hh);
        float w01 = wcat(n, kb + 1, W_ih, W_hh, b_ih, b_hh);
        float w10 = wcat(n, kb + 8, W_ih, W_hh, b_ih, b_hh);
        float w11 = wcat(n, kb + 9, W_ih, W_hh, b_ih, b_hh);
        u32 h00 = bf16hi_u(w00), h01 = bf16hi_u(w01);
        u32 h10 = bf16hi_u(w10), h11 = bf16hi_u(w11);
        uint4 e;
        e.x = prmt_pack(h00, h01);
        e.y = prmt_pack(h10, h11);
        e.z = bf16x2_rn(w00 - __uint_as_float(h00), w01 - __uint_as_float(h01));
        e.w = bf16x2_rn(w10 - __uint_as_float(h10), w11 - __uint_as_float(h11));
        Bs[idx] = e;
    }

    // ---- per-warp slab init: zeros (incl. col 67), bias col 66 = 1 ----
#pragma unroll
    for (int i = lane; i < SLAB_FLOATS / 4; i += 32)
        *reinterpret_cast<float4*>(slab + 4 * i) = make_float4(0, 0, 0, 0);
    __syncwarp();
    slab[lane * PITCH + 66] = 1.0f;     // one row per lane
    __syncthreads();

    // ---- prefetch x(t=0) into slab via cp.async (9 quads/lane, exact) ----
#pragma unroll
    for (int k = 0; k < 9; k++) {
        int i = lane + 32 * k;          // 0..287 = 32 rows * 9 quads
        int rr = i / 9, q = i - rr * 9;
        CP16(slab_u + (rr * PITCH + 4 * q) * 4,
             x + (size_t)(wB + rr) * (NT * NIn) + 4 * q);
    }
    CP_COMMIT();

    const int r    = lane >> 2;               // frag row 0..7
    const bool ev  = (lane & 1) == 0;
    const int rowp = r + (ev ? 0 : 8);        // m0 cell row; m1 = rowp+16
    const int hsel = (lane >> 1) & 1;         // hh = 2j + hsel
    const int kofs = 2 * (lane & 3);

    float c0[NTILE], c1[NTILE];
#pragma unroll
    for (int j = 0; j < NTILE; j++) { c0[j] = 0.0f; c1[j] = 0.0f; }

    for (int t = 0; t < NT; t++) {
        CP_WAIT0();
        __syncwarp();                         // x(t) and h(t-1) visible

        // ---- build all A fragments for this timestep (80 regs) ----
        u32 A[NCHUNK][16];
#pragma unroll
        for (int ch = 0; ch < NCHUNK; ch++) {
            int kb = 16 * ch + kofs;
            mk_ahl(*reinterpret_cast<const float2*>(slab + r * PITCH + kb),            A[ch][0], A[ch][4]);
            mk_ahl(*reinterpret_cast<const float2*>(slab + (r + 8) * PITCH + kb),      A[ch][1], A[ch][5]);
            mk_ahl(*reinterpret_cast<const float2*>(slab + r * PITCH + kb + 8),        A[ch][2], A[ch][6]);
            mk_ahl(*reinterpret_cast<const float2*>(slab + (r + 8) * PITCH + kb + 8),  A[ch][3], A[ch][7]);
            mk_ahl(*reinterpret_cast<const float2*>(slab + (r + 16) * PITCH + kb),     A[ch][8], A[ch][12]);
            mk_ahl(*reinterpret_cast<const float2*>(slab + (r + 24) * PITCH + kb),     A[ch][9], A[ch][13]);
            mk_ahl(*reinterpret_cast<const float2*>(slab + (r + 16) * PITCH + kb + 8), A[ch][10], A[ch][14]);
            mk_ahl(*reinterpret_cast<const float2*>(slab + (r + 24) * PITCH + kb + 8), A[ch][11], A[ch][15]);
        }
        // NOTE: ch=4 reads cols 68..79 = finite garbage; B is 0 there.

        // ---- prefetch x(t+1): slab x-cols free (A frags are in regs) ----
        if (t < NT - 1) {
#pragma unroll
            for (int k = 0; k < 9; k++) {
                int i = lane + 32 * k;
                int rr = i / 9, q = i - rr * 9;
                CP16(slab_u + (rr * PITCH + 4 * q) * 4,
                     x + (size_t)(wB + rr) * (NT * NIn) + (t + 1) * NIn + 4 * q);
            }
            CP_COMMIT();
        }

        // ---- per-tile GEMM + epilogue (j outer, D transient) ----
#pragma unroll
        for (int j = 0; j < NTILE; j++) {
            float D[8];
#pragma unroll
            for (int i = 0; i < 8; i++) D[i] = 0.0f;
#pragma unroll
            for (int ch = 0; ch < NCHUNK; ch++) {
                uint4 B = Bs[(ch * NTILE + j) * 32 + lane];
                mma_bf16(D,     A[ch][0], A[ch][1], A[ch][2],  A[ch][3],  B.x, B.y);  // m0 hi*hi
                mma_bf16(D + 4, A[ch][8], A[ch][9], A[ch][10], A[ch][11], B.x, B.y);  // m1 hi*hi
                mma_bf16(D,     A[ch][4], A[ch][5], A[ch][6],  A[ch][7],  B.x, B.y);  // m0 lo*hi
                mma_bf16(D + 4, A[ch][12],A[ch][13],A[ch][14], A[ch][15], B.x, B.y);  // m1 lo*hi
                mma_bf16(D,     A[ch][0], A[ch][1], A[ch][2],  A[ch][3],  B.z, B.w);  // m0 hi*lo
                mma_bf16(D + 4, A[ch][8], A[ch][9], A[ch][10], A[ch][11], B.z, B.w);  // m1 hi*lo
            }
#pragma unroll
            for (int m = 0; m < 2; m++) {
                float* Dm = D + 4 * m;
                float d0 = Dm[0], d1 = Dm[1], d2 = Dm[2], d3 = Dm[3];
                float e0 = __shfl_xor_sync(0xffffffffu, d0, 1);
                float e1 = __shfl_xor_sync(0xffffffffu, d1, 1);
                float e2 = __shfl_xor_sync(0xffffffffu, d2, 1);
                float e3 = __shfl_xor_sync(0xffffffffu, d3, 1);
                float gi = ev ? d0 : e2;
                float gf = ev ? d1 : e3;
                float gg = ev ? e0 : d2;
                float go = ev ? e1 : d3;
                float it = sigmoid_f(gi), ft = sigmoid_f(gf);
                float gt = tanh_f(gg),    ot = sigmoid_f(go);
                float* cr = m ? c1 : c0;
                float cn = fmaf(ft, cr[j], it * gt);
                cr[j] = cn;
                slab[(rowp + 16 * m) * PITCH + 36 + (2 * j + hsel)] = ot * tanh_f(cn);
            }
        }
        __syncwarp();

        // ---- out write: 32 rows x 30 from slab h cols ----
#pragma unroll
        for (int k = 0; k < 30; k++) {
            int i = lane + 32 * k;                  // < 960
            int rr = i / 30, cc = i - rr * 30;
            out[(size_t)(wB + rr) * (NT * NH) + t * NH + cc] =
                slab[rr * PITCH + 36 + cc];
        }
        __syncwarp();   // h reads done before next t's A-frag build
    }

    // ---- final states ----
    float* hN = out + (size_t)NB * NT * NH;
    float* cN = hN + (size_t)NB * NH;
#pragma unroll
    for (int k = 0; k < 30; k++) {
        int i = lane + 32 * k;
        int rr = i / 30, cc = i - rr * 30;
        hN[(size_t)(wB + rr) * NH + cc] = slab[rr * PITCH + 36 + cc];
    }
    __syncwarp();
#pragma unroll
    for (int j = 0; j < NTILE; j++) {
        slab[rowp * PITCH + 36 + (2 * j + hsel)]        = c0[j];
        slab[(rowp + 16) * PITCH + 36 + (2 * j + hsel)] = c1[j];
    }
    __syncwarp();
#pragma unroll
    for (int k = 0; k < 30; k++) {
        int i = lane + 32 * k;
        int rr = i / 30, cc = i - rr * 30;
        cN[(size_t)(wB + rr) * NH + cc] = slab[rr * PITCH + 36 + cc];
    }
}

extern "C" void kernel_launch(void* const* d_in, const int* in_sizes, int n_in,
                              void* d_out, int out_size) {
    const float* x    = (const float*)d_in[0];
    const float* W_ih = (const float*)d_in[1];
    const float* W_hh = (const float*)d_in[2];
    const float* b_ih = (const float*)d_in[3];
    const float* b_hh = (const float*)d_in[4];
    float* out = (float*)d_out;

    cudaFuncSetAttribute(lstm_hmma_jo,
                         cudaFuncAttributeMaxDynamicSharedMemorySize, SMEM_BYTES);
    lstm_hmma_jo<<<GRID, BLOCK, SMEM_BYTES>>>(x, W_ih, W_hh, b_ih, b_hh, out);
}